// round 12
// baseline (speedup 1.0000x reference)
#include <cuda_runtime.h>
#include <math.h>
#include <stdint.h>

#define Bn    2
#define Hh    64
#define Ww    2048
#define COUTC 64
#define NPIX  (Hh*Ww)
#define NTOT  (Bn*NPIX)

#define TILE    256
#define TW      258
#define THREADS 512

// smem layout (float offsets)
#define S_PN   0                    // [3ch][3r][258] = 2322
#define S_RNG  2322                 // [3][258] = 774
#define S_A    3096                 // [64 c][64 o] = 4096 (16B aligned)
#define S_WCP  7192                 // [64 c][260 p] = 16640
#define S_W    23832                // [64 c][264 p] = 16896 (16B aligned rows)
#define S_A1   40728                // [9 k][260 p]
#define S_M    43068                // [9 k][260 p]
#define SMEM_FLOATS 45408
#define SMEM_BYTES  (SMEM_FLOATS*4)   // 181632 B

__device__ float  g_pre[(size_t)Bn*COUTC*NPIX];   // [b][o][n]
__device__ __align__(16) float g_aggT[9*64*64];   // [k][c][o]
__device__ double g_sum[COUTC];
__device__ double g_sumsq[COUTC];
__device__ float  g_scale[COUTC];
__device__ float  g_shift[COUTC];

__global__ void k_prep(const float* __restrict__ w_agg) {
    int idx = blockIdx.x * 256 + threadIdx.x;
    if (idx < 9*64*64) {
        int k = idx >> 12, c = (idx >> 6) & 63, o = idx & 63;
        g_aggT[idx] = w_agg[o*576 + k*64 + c];
    }
    if (blockIdx.x == 0 && threadIdx.x < COUTC) {
        g_sum[threadIdx.x] = 0.0; g_sumsq[threadIdx.x] = 0.0;
    }
}

__global__ void __launch_bounds__(THREADS, 1)
k_main(const float* __restrict__ x, const int* __restrict__ mask,
       const float* __restrict__ w_spatial, const float* __restrict__ b_spatial,
       const float* __restrict__ w_channel, const float* __restrict__ b_channel) {
    extern __shared__ float sm[];
    const int tid = threadIdx.x;
    const int og  = tid & 7;       // output group: outputs [og*8, og*8+8)  (8 distinct per warp)
    const int pg  = tid >> 3;      // pixel quad: pixels [pg*4, pg*4+4)     (4 distinct per warp)
    const int b = blockIdx.z, h = blockIdx.y, w0 = blockIdx.x * TILE;

    const float* xb = x + (size_t)b * 67 * NPIX;

    // ---- pn tile (3 ch, 3 rows, halo) ----
    for (int idx = tid; idx < 3*3*TW; idx += THREADS) {
        int c = idx/(3*TW), rem = idx - c*3*TW, r = rem/TW, j = rem - r*TW;
        int gh = h + r - 1, gw = w0 + j - 1;
        float v = 0.f;
        if ((unsigned)gh < Hh && (unsigned)gw < Ww) v = xb[((size_t)c*Hh + gh)*Ww + gw];
        sm[S_PN + idx] = v;
    }
    __syncthreads();
    for (int idx = tid; idx < 3*TW; idx += THREADS) {
        float a = sm[S_PN+idx], bb = sm[S_PN+3*TW+idx], cc = sm[S_PN+6*TW+idx];
        sm[S_RNG + idx] = sqrtf(a*a + bb*bb + cc*cc);
    }
    __syncthreads();

    // ---- attention: threads 0..255, thread = pixel ----
    if (tid < 256) {
        const int p = tid, jc = p + 1;
        float cx = sm[S_PN + TW + jc];
        float cy = sm[S_PN + 3*TW + TW + jc];
        float cz = sm[S_PN + 6*TW + TW + jc];
        float cr = sm[S_RNG + TW + jc];
        float p0x[9], p0y[9], p0z[9], p0r[9], mk[9];
        const int* mrow = mask + (size_t)b * NPIX;
        #pragma unroll
        for (int k = 0; k < 9; k++) {
            int r = k/3, dj = k - r*3, off = r*TW + p + dj;
            p0x[k] = sm[S_PN + off]        - cx;
            p0y[k] = sm[S_PN + 3*TW + off] - cy;
            p0z[k] = sm[S_PN + 6*TW + off] - cz;
            p0r[k] = sm[S_RNG + off]       - cr;
            int gh = h + r - 1, gw = w0 + p + dj - 1;
            mk[k] = ((unsigned)gh < Hh && (unsigned)gw < Ww) ? (float)mrow[gh*Ww + gw] : 0.f;
        }
        float wsv[9];
        #pragma unroll
        for (int k = 0; k < 9; k++) wsv[k] = -1e30f;
        float wcp[64], wcmax = -1e30f;
        #pragma unroll
        for (int c = 0; c < 64; c++) {
            float4 w4 = __ldg((const float4*)w_spatial + c);
            float4 v4 = __ldg((const float4*)w_channel + c);
            float bs = __ldg(b_spatial + c), bc = __ldg(b_channel + c);
            float wcc = -1e30f;
            #pragma unroll
            for (int k = 0; k < 9; k++) {
                float ds = fmaf(p0x[k], w4.x, fmaf(p0y[k], w4.y, fmaf(p0z[k], w4.z, fmaf(p0r[k], w4.w, bs))));
                float dc = fmaf(p0x[k], v4.x, fmaf(p0y[k], v4.y, fmaf(p0z[k], v4.z, fmaf(p0r[k], v4.w, bc))));
                wsv[k] = fmaxf(wsv[k], ds);
                wcc    = fmaxf(wcc, dc);
            }
            wcp[c] = wcc;
            wcmax = fmaxf(wcmax, wcc);
        }
        float wmax = wsv[0];
        #pragma unroll
        for (int k = 1; k < 9; k++) wmax = fmaxf(wmax, wsv[k]);
        float ssum = 0.f;
        #pragma unroll
        for (int k = 0; k < 9; k++) { wsv[k] = __expf(wsv[k] - wmax); ssum += wsv[k]; }
        float sinv = 1.f / ssum;
        float csum = 0.f;
        #pragma unroll
        for (int c = 0; c < 64; c++) { float e = __expf(wcp[c] - wcmax); wcp[c] = e; csum += e; }
        float cinv = 1.f / csum;
        #pragma unroll
        for (int k = 0; k < 9; k++) {
            sm[S_A1 + k*260 + p] = wsv[k]*sinv*mk[k];
            sm[S_M  + k*260 + p] = mk[k];
        }
        #pragma unroll
        for (int c = 0; c < 64; c++) sm[S_WCP + c*260 + p] = wcp[c]*cinv;
    }

    // ---- GEMM: 4 pixels x 8 outputs per thread, software-pipelined feature LDGs ----
    unsigned long long acc[16];
    #pragma unroll
    for (int i = 0; i < 16; i++) acc[i] = 0ull;

    // materialize split: 2 threads per pixel, 32 channels each
    const int mp  = tid & 255;            // pixel
    const int mc0 = (tid >> 8) * 32;      // channel start
    float fv[32];

    // prefetch features for k=0
    {
        const int gh = h - 1, gw = w0 + mp - 1;
        const bool valid = ((unsigned)gh < Hh) && ((unsigned)gw < Ww);
        const float* fptr = xb + (size_t)(3 + mc0)*NPIX + (size_t)gh*Ww + gw;
        #pragma unroll
        for (int cc = 0; cc < 32; cc++)
            fv[cc] = valid ? __ldg(fptr + (size_t)cc*NPIX) : 0.f;
    }

    for (int k9 = 0; k9 < 9; k9++) {
        __syncthreads();   // previous k's s_A/s_W reads complete
        // stage A[k9] (64x64): 1024 float4s over 512 threads
        {
            const float4* src = (const float4*)(g_aggT + k9*4096);
            float4* dst = (float4*)(sm + S_A);
            dst[tid]       = src[tid];
            dst[512 + tid] = src[512 + tid];
        }
        // write W[c][p] from prefetched fv
        {
            float amk = sm[S_A1 + k9*260 + mp];
            float mkk = sm[S_M  + k9*260 + mp];
            #pragma unroll 8
            for (int cc = 0; cc < 32; cc++) {
                float wf = fmaf(mkk, sm[S_WCP + (mc0 + cc)*260 + mp], amk) * fv[cc];
                sm[S_W + (mc0 + cc)*264 + mp] = wf;
            }
        }
        __syncthreads();

        // prefetch features for k9+1 (latency hides under GEMM below)
        if (k9 < 8) {
            const int kn = k9 + 1;
            const int rr = kn/3, dj = kn - rr*3;
            const int gh = h + rr - 1, gw = w0 + mp + dj - 1;
            const bool valid = ((unsigned)gh < Hh) && ((unsigned)gw < Ww);
            const float* fptr = xb + (size_t)(3 + mc0)*NPIX + (size_t)gh*Ww + gw;
            #pragma unroll
            for (int cc = 0; cc < 32; cc++)
                fv[cc] = valid ? __ldg(fptr + (size_t)cc*NPIX) : 0.f;
        }

        #pragma unroll 2
        for (int c = 0; c < 64; c++) {
            float4 wv = *(const float4*)(sm + S_W + c*264 + pg*4);
            const ulonglong2* ar = (const ulonglong2*)(sm + S_A + c*64 + og*8);
            ulonglong2 aL = ar[0];   // output pairs (o0,o1),(o2,o3)
            ulonglong2 aH = ar[1];   // (o4,o5),(o6,o7)
            #define DO_PIX(i, w) { \
                unsigned long long wf2; \
                asm("mov.b64 %0, {%1, %1};" : "=l"(wf2) : "f"(w)); \
                asm("fma.rn.f32x2 %0, %1, %2, %0;" : "+l"(acc[(i)*4+0]) : "l"(aL.x), "l"(wf2)); \
                asm("fma.rn.f32x2 %0, %1, %2, %0;" : "+l"(acc[(i)*4+1]) : "l"(aL.y), "l"(wf2)); \
                asm("fma.rn.f32x2 %0, %1, %2, %0;" : "+l"(acc[(i)*4+2]) : "l"(aH.x), "l"(wf2)); \
                asm("fma.rn.f32x2 %0, %1, %2, %0;" : "+l"(acc[(i)*4+3]) : "l"(aH.y), "l"(wf2)); }
            DO_PIX(0, wv.x) DO_PIX(1, wv.y) DO_PIX(2, wv.z) DO_PIX(3, wv.w)
            #undef DO_PIX
        }
    }

    // ---- epilogue: stage [o][p] in s_W ----
    __syncthreads();
    #pragma unroll
    for (int i = 0; i < 4; i++) {
        #pragma unroll
        for (int j = 0; j < 4; j++) {
            float lo, hi;
            asm("mov.b64 {%0, %1}, %2;" : "=f"(lo), "=f"(hi) : "l"(acc[i*4+j]));
            sm[S_W + (og*8 + 2*j    )*264 + pg*4 + i] = lo;
            sm[S_W + (og*8 + 2*j + 1)*264 + pg*4 + i] = hi;
        }
    }
    __syncthreads();
    {
        const size_t n0 = (size_t)h * Ww + w0;
        float* gp = g_pre + (size_t)b * COUTC * NPIX;
        #pragma unroll
        for (int t = 0; t < 8; t++) {
            int idx = t*512 + tid;        // 0..4095 float4s
            int o = idx >> 6, p4 = idx & 63;
            float4 v = *(const float4*)&sm[S_W + o*264 + p4*4];
            *(float4*)(gp + (size_t)o*NPIX + n0 + p4*4) = v;
        }
    }
}

__global__ void k_stats() {
    int o = blockIdx.x, slab = blockIdx.y, tid = threadIdx.x;
    size_t base = (slab < 8)
        ? ((size_t)o * NPIX + (size_t)slab * 16384)
        : ((size_t)(COUTC + o) * NPIX + (size_t)(slab - 8) * 16384);
    const float4* p = (const float4*)(g_pre + base);
    float s = 0.f, s2 = 0.f;
    #pragma unroll 4
    for (int i = tid; i < 4096; i += 256) {
        float4 v = p[i];
        s  += v.x + v.y + v.z + v.w;
        s2 += v.x*v.x + v.y*v.y + v.z*v.z + v.w*v.w;
    }
    #pragma unroll
    for (int off = 16; off; off >>= 1) {
        s  += __shfl_down_sync(0xffffffffu, s,  off);
        s2 += __shfl_down_sync(0xffffffffu, s2, off);
    }
    __shared__ float rs[8], rq[8];
    int wrp = tid >> 5, lane = tid & 31;
    if (lane == 0) { rs[wrp] = s; rq[wrp] = s2; }
    __syncthreads();
    if (tid == 0) {
        float a = 0.f, q = 0.f;
        #pragma unroll
        for (int i = 0; i < 8; i++) { a += rs[i]; q += rq[i]; }
        atomicAdd(&g_sum[o],   (double)a);
        atomicAdd(&g_sumsq[o], (double)q);
    }
}

__global__ void k_final(const float* __restrict__ gamma, const float* __restrict__ beta) {
    int o = threadIdx.x;
    double N = (double)NTOT;
    double mean = g_sum[o] / N;
    double var  = g_sumsq[o] / N - mean * mean;
    if (var < 0.0) var = 0.0;
    float sc = gamma[o] * (float)(1.0 / sqrt(var + 1e-5));
    g_scale[o] = sc;
    g_shift[o] = beta[o] - (float)mean * sc;
}

__global__ void k_norm(float* __restrict__ out) {
    int i = blockIdx.x * 256 + threadIdx.x;
    float4 v = ((const float4*)g_pre)[i];
    int o = (i >> 15) & 63;
    float sc = g_scale[o], sh = g_shift[o];
    float4 r;
    r.x = fmaxf(0.f, v.x * sc + sh);
    r.y = fmaxf(0.f, v.y * sc + sh);
    r.z = fmaxf(0.f, v.z * sc + sh);
    r.w = fmaxf(0.f, v.w * sc + sh);
    ((float4*)out)[i] = r;
}

extern "C" void kernel_launch(void* const* d_in, const int* in_sizes, int n_in,
                              void* d_out, int out_size) {
    const float* x         = (const float*)d_in[0];
    const int*   mask      = (const int*)  d_in[1];
    const float* w_spatial = (const float*)d_in[2];
    const float* b_spatial = (const float*)d_in[3];
    const float* w_channel = (const float*)d_in[4];
    const float* b_channel = (const float*)d_in[5];
    const float* w_agg     = (const float*)d_in[6];
    const float* gamma     = (const float*)d_in[7];
    const float* beta      = (const float*)d_in[8];
    float* out = (float*)d_out;

    cudaFuncSetAttribute(k_main, cudaFuncAttributeMaxDynamicSharedMemorySize, SMEM_BYTES);

    k_prep<<<144, 256>>>(w_agg);
    dim3 grid(Ww / TILE, Hh, Bn);   // (8, 64, 2)
    k_main<<<grid, THREADS, SMEM_BYTES>>>(x, mask, w_spatial, b_spatial, w_channel, b_channel);
    k_stats<<<dim3(COUTC, 16), 256>>>();
    k_final<<<1, COUTC>>>(gamma, beta);
    k_norm<<<16384, 256>>>(out);
}

// round 13
// speedup vs baseline: 1.0325x; 1.0325x over previous
#include <cuda_runtime.h>
#include <math.h>
#include <stdint.h>

#define Bn    2
#define Hh    64
#define Ww    2048
#define COUTC 64
#define NPIX  (Hh*Ww)
#define NTOT  (Bn*NPIX)

#define TILE    256
#define TW      258
#define THREADS 512

// smem layout (float offsets)
#define S_PN   0                    // [3ch][3r][258] = 2322
#define S_RNG  2322                 // [3][258] = 774
#define S_A    3096                 // [64 c][64 o] = 4096 (16B aligned)
#define S_WCP  7192                 // [64 c][260 p] = 16640
#define S_W    23832                // [64 c][264 p] = 16896 (16B aligned rows)
#define S_A1   40728                // [9 k][260 p]
#define S_M    43068                // [9 k][260 p]
#define SMEM_FLOATS 45408
#define SMEM_BYTES  (SMEM_FLOATS*4)   // 181632 B

__device__ float  g_pre[(size_t)Bn*COUTC*NPIX];   // [b][o][n]
__device__ __align__(16) float g_aggT[9*64*64];   // [k][c][o]
__device__ double g_sum[COUTC];
__device__ double g_sumsq[COUTC];
__device__ float  g_scale[COUTC];
__device__ float  g_shift[COUTC];

__global__ void k_prep(const float* __restrict__ w_agg) {
    int idx = blockIdx.x * 256 + threadIdx.x;
    if (idx < 9*64*64) {
        int k = idx >> 12, c = (idx >> 6) & 63, o = idx & 63;
        g_aggT[idx] = w_agg[o*576 + k*64 + c];
    }
    if (blockIdx.x == 0 && threadIdx.x < COUTC) {
        g_sum[threadIdx.x] = 0.0; g_sumsq[threadIdx.x] = 0.0;
    }
}

__global__ void __launch_bounds__(THREADS, 1)
k_main(const float* __restrict__ x, const int* __restrict__ mask,
       const float* __restrict__ w_spatial, const float* __restrict__ b_spatial,
       const float* __restrict__ w_channel, const float* __restrict__ b_channel) {
    extern __shared__ float sm[];
    const int tid = threadIdx.x;
    const int og  = tid & 7;       // outputs [og*8, og*8+8)  — 8 distinct per warp
    const int pg  = tid >> 3;      // pixels  [pg*4, pg*4+4)  — 4 distinct per warp
    const int b = blockIdx.z, h = blockIdx.y, w0 = blockIdx.x * TILE;

    const float* xb = x + (size_t)b * 67 * NPIX;

    // ---- pn tile (3 ch, 3 rows, halo) ----
    for (int idx = tid; idx < 3*3*TW; idx += THREADS) {
        int c = idx/(3*TW), rem = idx - c*3*TW, r = rem/TW, j = rem - r*TW;
        int gh = h + r - 1, gw = w0 + j - 1;
        float v = 0.f;
        if ((unsigned)gh < Hh && (unsigned)gw < Ww) v = xb[((size_t)c*Hh + gh)*Ww + gw];
        sm[S_PN + idx] = v;
    }
    __syncthreads();
    for (int idx = tid; idx < 3*TW; idx += THREADS) {
        float a = sm[S_PN+idx], bb = sm[S_PN+3*TW+idx], cc = sm[S_PN+6*TW+idx];
        sm[S_RNG + idx] = sqrtf(a*a + bb*bb + cc*cc);
    }
    __syncthreads();

    // ---- attention: threads 0..255, thread = pixel ----
    if (tid < 256) {
        const int p = tid, jc = p + 1;
        float cx = sm[S_PN + TW + jc];
        float cy = sm[S_PN + 3*TW + TW + jc];
        float cz = sm[S_PN + 6*TW + TW + jc];
        float cr = sm[S_RNG + TW + jc];
        float p0x[9], p0y[9], p0z[9], p0r[9], mk[9];
        const int* mrow = mask + (size_t)b * NPIX;
        #pragma unroll
        for (int k = 0; k < 9; k++) {
            int r = k/3, dj = k - r*3, off = r*TW + p + dj;
            p0x[k] = sm[S_PN + off]        - cx;
            p0y[k] = sm[S_PN + 3*TW + off] - cy;
            p0z[k] = sm[S_PN + 6*TW + off] - cz;
            p0r[k] = sm[S_RNG + off]       - cr;
            int gh = h + r - 1, gw = w0 + p + dj - 1;
            mk[k] = ((unsigned)gh < Hh && (unsigned)gw < Ww) ? (float)mrow[gh*Ww + gw] : 0.f;
        }
        float wsv[9];
        #pragma unroll
        for (int k = 0; k < 9; k++) wsv[k] = -1e30f;
        float wcp[64], wcmax = -1e30f;
        #pragma unroll
        for (int c = 0; c < 64; c++) {
            float4 w4 = __ldg((const float4*)w_spatial + c);
            float4 v4 = __ldg((const float4*)w_channel + c);
            float bs = __ldg(b_spatial + c), bc = __ldg(b_channel + c);
            float wcc = -1e30f;
            #pragma unroll
            for (int k = 0; k < 9; k++) {
                float ds = fmaf(p0x[k], w4.x, fmaf(p0y[k], w4.y, fmaf(p0z[k], w4.z, fmaf(p0r[k], w4.w, bs))));
                float dc = fmaf(p0x[k], v4.x, fmaf(p0y[k], v4.y, fmaf(p0z[k], v4.z, fmaf(p0r[k], v4.w, bc))));
                wsv[k] = fmaxf(wsv[k], ds);
                wcc    = fmaxf(wcc, dc);
            }
            wcp[c] = wcc;
            wcmax = fmaxf(wcmax, wcc);
        }
        float wmax = wsv[0];
        #pragma unroll
        for (int k = 1; k < 9; k++) wmax = fmaxf(wmax, wsv[k]);
        float ssum = 0.f;
        #pragma unroll
        for (int k = 0; k < 9; k++) { wsv[k] = __expf(wsv[k] - wmax); ssum += wsv[k]; }
        float sinv = 1.f / ssum;
        float csum = 0.f;
        #pragma unroll
        for (int c = 0; c < 64; c++) { float e = __expf(wcp[c] - wcmax); wcp[c] = e; csum += e; }
        float cinv = 1.f / csum;
        #pragma unroll
        for (int k = 0; k < 9; k++) {
            sm[S_A1 + k*260 + p] = wsv[k]*sinv*mk[k];
            sm[S_M  + k*260 + p] = mk[k];
        }
        #pragma unroll
        for (int c = 0; c < 64; c++) sm[S_WCP + c*260 + p] = wcp[c]*cinv;
    }

    // ---- GEMM: 4 pixels x 8 outputs per thread ----
    unsigned long long acc[16];
    #pragma unroll
    for (int i = 0; i < 16; i++) acc[i] = 0ull;

    // materialize split: 2 threads per pixel, 32 channels each
    const int mp  = tid & 255;            // pixel
    const int mc0 = (tid >> 8) * 32;      // channel start

    for (int k9 = 0; k9 < 9; k9++) {
        __syncthreads();   // previous k's s_A/s_W reads complete
        // stage A[k9] (64x64): 1024 float4s over 512 threads
        {
            const float4* src = (const float4*)(g_aggT + k9*4096);
            float4* dst = (float4*)(sm + S_A);
            dst[tid]       = src[tid];
            dst[512 + tid] = src[512 + tid];
        }
        // materialize W[c][p]
        {
            const int rr = k9/3, dj = k9 - rr*3;
            const int gh = h + rr - 1, gw = w0 + mp + dj - 1;
            const bool valid = ((unsigned)gh < Hh) && ((unsigned)gw < Ww);
            const float* fptr = xb + (size_t)(3 + mc0)*NPIX + (size_t)gh*Ww + gw;
            float amk = sm[S_A1 + k9*260 + mp];
            float mkk = sm[S_M  + k9*260 + mp];
            #pragma unroll 8
            for (int cc = 0; cc < 32; cc++) {
                float fv = valid ? __ldg(fptr + (size_t)cc*NPIX) : 0.f;
                float wf = fmaf(mkk, sm[S_WCP + (mc0 + cc)*260 + mp], amk) * fv;
                sm[S_W + (mc0 + cc)*264 + mp] = wf;
            }
        }
        __syncthreads();

        #pragma unroll 2
        for (int c = 0; c < 64; c++) {
            float4 wv = *(const float4*)(sm + S_W + c*264 + pg*4);
            const ulonglong2* ar = (const ulonglong2*)(sm + S_A + c*64 + og*8);
            ulonglong2 aL = ar[0];   // output pairs (o0,o1),(o2,o3)
            ulonglong2 aH = ar[1];   // (o4,o5),(o6,o7)
            #define DO_PIX(i, w) { \
                unsigned long long wf2; \
                asm("mov.b64 %0, {%1, %1};" : "=l"(wf2) : "f"(w)); \
                asm("fma.rn.f32x2 %0, %1, %2, %0;" : "+l"(acc[(i)*4+0]) : "l"(aL.x), "l"(wf2)); \
                asm("fma.rn.f32x2 %0, %1, %2, %0;" : "+l"(acc[(i)*4+1]) : "l"(aL.y), "l"(wf2)); \
                asm("fma.rn.f32x2 %0, %1, %2, %0;" : "+l"(acc[(i)*4+2]) : "l"(aH.x), "l"(wf2)); \
                asm("fma.rn.f32x2 %0, %1, %2, %0;" : "+l"(acc[(i)*4+3]) : "l"(aH.y), "l"(wf2)); }
            DO_PIX(0, wv.x) DO_PIX(1, wv.y) DO_PIX(2, wv.z) DO_PIX(3, wv.w)
            #undef DO_PIX
        }
    }

    // ---- epilogue: stage [o][p] in s_W ----
    __syncthreads();
    #pragma unroll
    for (int i = 0; i < 4; i++) {
        #pragma unroll
        for (int j = 0; j < 4; j++) {
            float lo, hi;
            asm("mov.b64 {%0, %1}, %2;" : "=f"(lo), "=f"(hi) : "l"(acc[i*4+j]));
            sm[S_W + (og*8 + 2*j    )*264 + pg*4 + i] = lo;
            sm[S_W + (og*8 + 2*j + 1)*264 + pg*4 + i] = hi;
        }
    }
    __syncthreads();
    {
        const size_t n0 = (size_t)h * Ww + w0;
        float* gp = g_pre + (size_t)b * COUTC * NPIX;
        #pragma unroll
        for (int t = 0; t < 8; t++) {
            int idx = t*512 + tid;        // 0..4095 float4s
            int o = idx >> 6, p4 = idx & 63;
            float4 v = *(const float4*)&sm[S_W + o*264 + p4*4];
            *(float4*)(gp + (size_t)o*NPIX + n0 + p4*4) = v;
        }
    }
}

__global__ void k_stats() {
    int o = blockIdx.x, slab = blockIdx.y, tid = threadIdx.x;
    size_t base = (slab < 8)
        ? ((size_t)o * NPIX + (size_t)slab * 16384)
        : ((size_t)(COUTC + o) * NPIX + (size_t)(slab - 8) * 16384);
    const float4* p = (const float4*)(g_pre + base);
    float s = 0.f, s2 = 0.f;
    #pragma unroll 4
    for (int i = tid; i < 4096; i += 256) {
        float4 v = p[i];
        s  += v.x + v.y + v.z + v.w;
        s2 += v.x*v.x + v.y*v.y + v.z*v.z + v.w*v.w;
    }
    #pragma unroll
    for (int off = 16; off; off >>= 1) {
        s  += __shfl_down_sync(0xffffffffu, s,  off);
        s2 += __shfl_down_sync(0xffffffffu, s2, off);
    }
    __shared__ float rs[8], rq[8];
    int wrp = tid >> 5, lane = tid & 31;
    if (lane == 0) { rs[wrp] = s; rq[wrp] = s2; }
    __syncthreads();
    if (tid == 0) {
        float a = 0.f, q = 0.f;
        #pragma unroll
        for (int i = 0; i < 8; i++) { a += rs[i]; q += rq[i]; }
        atomicAdd(&g_sum[o],   (double)a);
        atomicAdd(&g_sumsq[o], (double)q);
    }
}

__global__ void k_final(const float* __restrict__ gamma, const float* __restrict__ beta) {
    int o = threadIdx.x;
    double N = (double)NTOT;
    double mean = g_sum[o] / N;
    double var  = g_sumsq[o] / N - mean * mean;
    if (var < 0.0) var = 0.0;
    float sc = gamma[o] * (float)(1.0 / sqrt(var + 1e-5));
    g_scale[o] = sc;
    g_shift[o] = beta[o] - (float)mean * sc;
}

__global__ void k_norm(float* __restrict__ out) {
    int i = blockIdx.x * 256 + threadIdx.x;
    float4 v = ((const float4*)g_pre)[i];
    int o = (i >> 15) & 63;
    float sc = g_scale[o], sh = g_shift[o];
    float4 r;
    r.x = fmaxf(0.f, v.x * sc + sh);
    r.y = fmaxf(0.f, v.y * sc + sh);
    r.z = fmaxf(0.f, v.z * sc + sh);
    r.w = fmaxf(0.f, v.w * sc + sh);
    ((float4*)out)[i] = r;
}

extern "C" void kernel_launch(void* const* d_in, const int* in_sizes, int n_in,
                              void* d_out, int out_size) {
    const float* x         = (const float*)d_in[0];
    const int*   mask      = (const int*)  d_in[1];
    const float* w_spatial = (const float*)d_in[2];
    const float* b_spatial = (const float*)d_in[3];
    const float* w_channel = (const float*)d_in[4];
    const float* b_channel = (const float*)d_in[5];
    const float* w_agg     = (const float*)d_in[6];
    const float* gamma     = (const float*)d_in[7];
    const float* beta      = (const float*)d_in[8];
    float* out = (float*)d_out;

    cudaFuncSetAttribute(k_main, cudaFuncAttributeMaxDynamicSharedMemorySize, SMEM_BYTES);

    k_prep<<<144, 256>>>(w_agg);
    dim3 grid(Ww / TILE, Hh, Bn);   // (8, 64, 2)
    k_main<<<grid, THREADS, SMEM_BYTES>>>(x, mask, w_spatial, b_spatial, w_channel, b_channel);
    k_stats<<<dim3(COUTC, 16), 256>>>();
    k_final<<<1, COUTC>>>(gamma, beta);
    k_norm<<<16384, 256>>>(out);
}

// round 14
// speedup vs baseline: 2.3968x; 2.3214x over previous
#include <cuda_runtime.h>
#include <math.h>
#include <stdint.h>

#define Bn    2
#define Hh    64
#define Ww    2048
#define COUTC 64
#define NPIX  (Hh*Ww)
#define NTOT  (Bn*NPIX)

#define TILE    256
#define TW      258
#define THREADS 512

// smem layout (float offsets)
#define S_PN   0                    // [3ch][3r][258] = 2322
#define S_RNG  2322                 // [3][258] = 774
#define S_A    3096                 // [64 c][64 o] = 4096 (16B aligned)
#define S_WCP  7192                 // [64 c][260 p] = 16640
#define S_W    23832                // [64 c][264 p] = 16896 (16B aligned rows)
#define S_A1   40728                // [9 k][260 p]
#define S_M    43068                // [9 k][260 p]
#define S_WSP  45408                // [512][10] partial wsv
#define S_WCM  50528                // [512] partial wcmax
#define SMEM_FLOATS 51040
#define SMEM_BYTES  (SMEM_FLOATS*4)   // 204160 B

__device__ float  g_pre[(size_t)Bn*COUTC*NPIX];   // [b][o][n]
__device__ __align__(16) float g_aggT[9*64*64];   // [k][c][o]
__device__ double g_sum[COUTC];
__device__ double g_sumsq[COUTC];
__device__ float  g_scale[COUTC];
__device__ float  g_shift[COUTC];

__global__ void k_prep(const float* __restrict__ w_agg) {
    int idx = blockIdx.x * 256 + threadIdx.x;
    if (idx < 9*64*64) {
        int k = idx >> 12, c = (idx >> 6) & 63, o = idx & 63;
        g_aggT[idx] = w_agg[o*576 + k*64 + c];
    }
    if (blockIdx.x == 0 && threadIdx.x < COUTC) {
        g_sum[threadIdx.x] = 0.0; g_sumsq[threadIdx.x] = 0.0;
    }
}

__global__ void __launch_bounds__(THREADS, 1)
k_main(const float* __restrict__ x, const int* __restrict__ mask,
       const float* __restrict__ w_spatial, const float* __restrict__ b_spatial,
       const float* __restrict__ w_channel, const float* __restrict__ b_channel) {
    extern __shared__ float sm[];
    const int tid = threadIdx.x;
    const int og  = tid >> 6;      // outputs [og*8, og*8+8) — warp-uniform (broadcast A)
    const int pg  = tid & 63;      // pixels  [pg*4, pg*4+4)
    const int b = blockIdx.z, h = blockIdx.y, w0 = blockIdx.x * TILE;

    const float* xb = x + (size_t)b * 67 * NPIX;

    // ---- pn tile (3 ch, 3 rows, halo) ----
    for (int idx = tid; idx < 3*3*TW; idx += THREADS) {
        int c = idx/(3*TW), rem = idx - c*3*TW, r = rem/TW, j = rem - r*TW;
        int gh = h + r - 1, gw = w0 + j - 1;
        float v = 0.f;
        if ((unsigned)gh < Hh && (unsigned)gw < Ww) v = xb[((size_t)c*Hh + gh)*Ww + gw];
        sm[S_PN + idx] = v;
    }
    __syncthreads();
    for (int idx = tid; idx < 3*TW; idx += THREADS) {
        float a = sm[S_PN+idx], bb = sm[S_PN+3*TW+idx], cc = sm[S_PN+6*TW+idx];
        sm[S_RNG + idx] = sqrtf(a*a + bb*bb + cc*cc);
    }
    __syncthreads();

    // ---- attention phase 1: ALL 512 threads; 2 threads/pixel, 32 channels each ----
    float mk[9];
    {
        const int p  = tid & 255;
        const int c0 = (tid >> 8) * 32;
        const int jc = p + 1;
        float cx = sm[S_PN + TW + jc];
        float cy = sm[S_PN + 3*TW + TW + jc];
        float cz = sm[S_PN + 6*TW + TW + jc];
        float cr = sm[S_RNG + TW + jc];
        float p0x[9], p0y[9], p0z[9], p0r[9];
        const int* mrow = mask + (size_t)b * NPIX;
        #pragma unroll
        for (int k = 0; k < 9; k++) {
            int r = k/3, dj = k - r*3, off = r*TW + p + dj;
            p0x[k] = sm[S_PN + off]        - cx;
            p0y[k] = sm[S_PN + 3*TW + off] - cy;
            p0z[k] = sm[S_PN + 6*TW + off] - cz;
            p0r[k] = sm[S_RNG + off]       - cr;
            int gh = h + r - 1, gw = w0 + p + dj - 1;
            mk[k] = ((unsigned)gh < Hh && (unsigned)gw < Ww) ? (float)mrow[gh*Ww + gw] : 0.f;
        }
        float wsv[9];
        #pragma unroll
        for (int k = 0; k < 9; k++) wsv[k] = -1e30f;
        float wcmax = -1e30f;
        #pragma unroll 4
        for (int ci = 0; ci < 32; ci++) {
            int c = c0 + ci;
            float4 w4 = __ldg((const float4*)w_spatial + c);
            float4 v4 = __ldg((const float4*)w_channel + c);
            float bs = __ldg(b_spatial + c), bc = __ldg(b_channel + c);
            float wcc = -1e30f;
            #pragma unroll
            for (int k = 0; k < 9; k++) {
                float ds = fmaf(p0x[k], w4.x, fmaf(p0y[k], w4.y, fmaf(p0z[k], w4.z, fmaf(p0r[k], w4.w, bs))));
                float dc = fmaf(p0x[k], v4.x, fmaf(p0y[k], v4.y, fmaf(p0z[k], v4.z, fmaf(p0r[k], v4.w, bc))));
                wsv[k] = fmaxf(wsv[k], ds);
                wcc    = fmaxf(wcc, dc);
            }
            sm[S_WCP + c*260 + p] = wcc;          // raw channel score
            wcmax = fmaxf(wcmax, wcc);
        }
        #pragma unroll
        for (int k = 0; k < 9; k++) sm[S_WSP + tid*10 + k] = wsv[k];
        sm[S_WCM + tid] = wcmax;
    }
    __syncthreads();

    // ---- attention phase 2: threads 0..255 combine + softmax ----
    if (tid < 256) {
        const int p = tid;
        float wsv[9];
        #pragma unroll
        for (int k = 0; k < 9; k++)
            wsv[k] = fmaxf(sm[S_WSP + p*10 + k], sm[S_WSP + (p+256)*10 + k]);
        float wcmax = fmaxf(sm[S_WCM + p], sm[S_WCM + p + 256]);
        float wmax = wsv[0];
        #pragma unroll
        for (int k = 1; k < 9; k++) wmax = fmaxf(wmax, wsv[k]);
        float ssum = 0.f;
        #pragma unroll
        for (int k = 0; k < 9; k++) { wsv[k] = __expf(wsv[k] - wmax); ssum += wsv[k]; }
        float sinv = 1.f / ssum;
        #pragma unroll
        for (int k = 0; k < 9; k++) {
            sm[S_A1 + k*260 + p] = wsv[k]*sinv*mk[k];
            sm[S_M  + k*260 + p] = mk[k];
        }
        // softmax over c: exp pass (sequential c order -> bit-identical csum)
        float csum = 0.f;
        #pragma unroll 8
        for (int c = 0; c < 64; c++) {
            float e = __expf(sm[S_WCP + c*260 + p] - wcmax);
            sm[S_WCP + c*260 + p] = e;
            csum += e;
        }
        float cinv = 1.f / csum;
        #pragma unroll 8
        for (int c = 0; c < 64; c++)
            sm[S_WCP + c*260 + p] *= cinv;
    }

    // ---- GEMM: 4 pixels x 8 outputs per thread (R10 mapping) ----
    unsigned long long acc[16];
    #pragma unroll
    for (int i = 0; i < 16; i++) acc[i] = 0ull;

    const int mp  = tid & 255;            // pixel
    const int mc0 = (tid >> 8) * 32;      // channel start

    // prefetch A tile for k=0
    float4 pA0, pA1;
    {
        const float4* src = (const float4*)g_aggT;
        pA0 = src[tid]; pA1 = src[512 + tid];
    }

    for (int k9 = 0; k9 < 9; k9++) {
        __syncthreads();   // previous k's s_A/s_W reads complete
        // store prefetched A[k9]
        {
            float4* dst = (float4*)(sm + S_A);
            dst[tid]       = pA0;
            dst[512 + tid] = pA1;
        }
        // materialize W[c][p]
        {
            const int rr = k9/3, dj = k9 - rr*3;
            const int gh = h + rr - 1, gw = w0 + mp + dj - 1;
            const bool valid = ((unsigned)gh < Hh) && ((unsigned)gw < Ww);
            const float* fptr = xb + (size_t)(3 + mc0)*NPIX + (size_t)gh*Ww + gw;
            float amk = sm[S_A1 + k9*260 + mp];
            float mkk = sm[S_M  + k9*260 + mp];
            #pragma unroll 8
            for (int cc = 0; cc < 32; cc++) {
                float fv = valid ? __ldg(fptr + (size_t)cc*NPIX) : 0.f;
                float wf = fmaf(mkk, sm[S_WCP + (mc0 + cc)*260 + mp], amk) * fv;
                sm[S_W + (mc0 + cc)*264 + mp] = wf;
            }
        }
        __syncthreads();

        // prefetch A for k9+1 (hides under GEMM below)
        if (k9 < 8) {
            const float4* src = (const float4*)(g_aggT + (k9+1)*4096);
            pA0 = src[tid]; pA1 = src[512 + tid];
        }

        #pragma unroll 2
        for (int c = 0; c < 64; c++) {
            float4 wv = *(const float4*)(sm + S_W + c*264 + pg*4);
            const ulonglong2* ar = (const ulonglong2*)(sm + S_A + c*64 + og*8);
            ulonglong2 aL = ar[0];   // output pairs (o0,o1),(o2,o3)
            ulonglong2 aH = ar[1];   // (o4,o5),(o6,o7)
            #define DO_PIX(i, w) { \
                unsigned long long wf2; \
                asm("mov.b64 %0, {%1, %1};" : "=l"(wf2) : "f"(w)); \
                asm("fma.rn.f32x2 %0, %1, %2, %0;" : "+l"(acc[(i)*4+0]) : "l"(aL.x), "l"(wf2)); \
                asm("fma.rn.f32x2 %0, %1, %2, %0;" : "+l"(acc[(i)*4+1]) : "l"(aL.y), "l"(wf2)); \
                asm("fma.rn.f32x2 %0, %1, %2, %0;" : "+l"(acc[(i)*4+2]) : "l"(aH.x), "l"(wf2)); \
                asm("fma.rn.f32x2 %0, %1, %2, %0;" : "+l"(acc[(i)*4+3]) : "l"(aH.y), "l"(wf2)); }
            DO_PIX(0, wv.x) DO_PIX(1, wv.y) DO_PIX(2, wv.z) DO_PIX(3, wv.w)
            #undef DO_PIX
        }
    }

    // ---- epilogue: stage [o][p] in s_W ----
    __syncthreads();
    #pragma unroll
    for (int i = 0; i < 4; i++) {
        #pragma unroll
        for (int j = 0; j < 4; j++) {
            float lo, hi;
            asm("mov.b64 {%0, %1}, %2;" : "=f"(lo), "=f"(hi) : "l"(acc[i*4+j]));
            sm[S_W + (og*8 + 2*j    )*264 + pg*4 + i] = lo;
            sm[S_W + (og*8 + 2*j + 1)*264 + pg*4 + i] = hi;
        }
    }
    __syncthreads();
    {
        const size_t n0 = (size_t)h * Ww + w0;
        float* gp = g_pre + (size_t)b * COUTC * NPIX;
        #pragma unroll
        for (int t = 0; t < 8; t++) {
            int idx = t*512 + tid;        // 0..4095 float4s
            int o = idx >> 6, p4 = idx & 63;
            float4 v = *(const float4*)&sm[S_W + o*264 + p4*4];
            *(float4*)(gp + (size_t)o*NPIX + n0 + p4*4) = v;
        }
    }
}

__global__ void k_stats() {
    int o = blockIdx.x, slab = blockIdx.y, tid = threadIdx.x;
    size_t base = (slab < 8)
        ? ((size_t)o * NPIX + (size_t)slab * 16384)
        : ((size_t)(COUTC + o) * NPIX + (size_t)(slab - 8) * 16384);
    const float4* p = (const float4*)(g_pre + base);
    float s = 0.f, s2 = 0.f;
    #pragma unroll 4
    for (int i = tid; i < 4096; i += 256) {
        float4 v = p[i];
        s  += v.x + v.y + v.z + v.w;
        s2 += v.x*v.x + v.y*v.y + v.z*v.z + v.w*v.w;
    }
    #pragma unroll
    for (int off = 16; off; off >>= 1) {
        s  += __shfl_down_sync(0xffffffffu, s,  off);
        s2 += __shfl_down_sync(0xffffffffu, s2, off);
    }
    __shared__ float rs[8], rq[8];
    int wrp = tid >> 5, lane = tid & 31;
    if (lane == 0) { rs[wrp] = s; rq[wrp] = s2; }
    __syncthreads();
    if (tid == 0) {
        float a = 0.f, q = 0.f;
        #pragma unroll
        for (int i = 0; i < 8; i++) { a += rs[i]; q += rq[i]; }
        atomicAdd(&g_sum[o],   (double)a);
        atomicAdd(&g_sumsq[o], (double)q);
    }
}

__global__ void k_final(const float* __restrict__ gamma, const float* __restrict__ beta) {
    int o = threadIdx.x;
    double N = (double)NTOT;
    double mean = g_sum[o] / N;
    double var  = g_sumsq[o] / N - mean * mean;
    if (var < 0.0) var = 0.0;
    float sc = gamma[o] * (float)(1.0 / sqrt(var + 1e-5));
    g_scale[o] = sc;
    g_shift[o] = beta[o] - (float)mean * sc;
}

__global__ void k_norm(float* __restrict__ out) {
    int i = blockIdx.x * 256 + threadIdx.x;
    float4 v = ((const float4*)g_pre)[i];
    int o = (i >> 15) & 63;
    float sc = g_scale[o], sh = g_shift[o];
    float4 r;
    r.x = fmaxf(0.f, v.x * sc + sh);
    r.y = fmaxf(0.f, v.y * sc + sh);
    r.z = fmaxf(0.f, v.z * sc + sh);
    r.w = fmaxf(0.f, v.w * sc + sh);
    ((float4*)out)[i] = r;
}

extern "C" void kernel_launch(void* const* d_in, const int* in_sizes, int n_in,
                              void* d_out, int out_size) {
    const float* x         = (const float*)d_in[0];
    const int*   mask      = (const int*)  d_in[1];
    const float* w_spatial = (const float*)d_in[2];
    const float* b_spatial = (const float*)d_in[3];
    const float* w_channel = (const float*)d_in[4];
    const float* b_channel = (const float*)d_in[5];
    const float* w_agg     = (const float*)d_in[6];
    const float* gamma     = (const float*)d_in[7];
    const float* beta      = (const float*)d_in[8];
    float* out = (float*)d_out;

    cudaFuncSetAttribute(k_main, cudaFuncAttributeMaxDynamicSharedMemorySize, SMEM_BYTES);

    k_prep<<<144, 256>>>(w_agg);
    dim3 grid(Ww / TILE, Hh, Bn);   // (8, 64, 2)
    k_main<<<grid, THREADS, SMEM_BYTES>>>(x, mask, w_spatial, b_spatial, w_channel, b_channel);
    k_stats<<<dim3(COUTC, 16), 256>>>();
    k_final<<<1, COUTC>>>(gamma, beta);
    k_norm<<<16384, 256>>>(out);
}

// round 15
// speedup vs baseline: 2.4982x; 1.0423x over previous
#include <cuda_runtime.h>
#include <math.h>
#include <stdint.h>

#define Bn    2
#define Hh    64
#define Ww    2048
#define COUTC 64
#define NPIX  (Hh*Ww)
#define NTOT  (Bn*NPIX)

#define TILE    128
#define TW      130
#define THREADS 256

// smem layout (float offsets)
#define S_PN   0                    // [3ch][3r][130] = 1170
#define S_RNG  1170                 // [3][130] = 390
#define S_A    1568                 // [64 c][64 o] = 4096 (16B aligned)
#define S_WCP  5664                 // [64 c][132 p] = 8448
#define S_W    14112                // [64 c][136 p] = 8704 (16B-aligned rows)
#define S_A1   22816                // [9 k][132 p] = 1188
#define S_M    24004                // [9 k][132 p] = 1188
#define S_WSP  25192                // [256][10] partial wsv = 2560
#define S_WCM  27752                // [256] partial wcmax
#define SMEM_FLOATS 28008
#define SMEM_BYTES  (SMEM_FLOATS*4)   // 112032 B  (2 CTAs = 219 KB <= 228 KB)

__device__ float  g_pre[(size_t)Bn*COUTC*NPIX];   // [b][o][n]
__device__ __align__(16) float g_aggT[9*64*64];   // [k][c][o]
__device__ double g_sum[COUTC];
__device__ double g_sumsq[COUTC];
__device__ float  g_scale[COUTC];
__device__ float  g_shift[COUTC];

__global__ void k_prep(const float* __restrict__ w_agg) {
    int idx = blockIdx.x * 256 + threadIdx.x;
    if (idx < 9*64*64) {
        int k = idx >> 12, c = (idx >> 6) & 63, o = idx & 63;
        g_aggT[idx] = w_agg[o*576 + k*64 + c];
    }
    if (blockIdx.x == 0 && threadIdx.x < COUTC) {
        g_sum[threadIdx.x] = 0.0; g_sumsq[threadIdx.x] = 0.0;
    }
}

__global__ void __launch_bounds__(THREADS, 2)
k_main(const float* __restrict__ x, const int* __restrict__ mask,
       const float* __restrict__ w_spatial, const float* __restrict__ b_spatial,
       const float* __restrict__ w_channel, const float* __restrict__ b_channel) {
    extern __shared__ float sm[];
    const int tid = threadIdx.x;
    const int og  = tid >> 5;      // outputs [og*8, og*8+8) — warp-uniform (broadcast A)
    const int pg  = tid & 31;      // pixels  [pg*4, pg*4+4)
    const int b = blockIdx.z, h = blockIdx.y, w0 = blockIdx.x * TILE;

    const float* xb = x + (size_t)b * 67 * NPIX;

    // ---- pn tile (3 ch, 3 rows, halo) ----
    for (int idx = tid; idx < 3*3*TW; idx += THREADS) {
        int c = idx/(3*TW), rem = idx - c*3*TW, r = rem/TW, j = rem - r*TW;
        int gh = h + r - 1, gw = w0 + j - 1;
        float v = 0.f;
        if ((unsigned)gh < Hh && (unsigned)gw < Ww) v = xb[((size_t)c*Hh + gh)*Ww + gw];
        sm[S_PN + idx] = v;
    }
    __syncthreads();
    for (int idx = tid; idx < 3*TW; idx += THREADS) {
        float a = sm[S_PN+idx], bb = sm[S_PN+3*TW+idx], cc = sm[S_PN+6*TW+idx];
        sm[S_RNG + idx] = sqrtf(a*a + bb*bb + cc*cc);
    }
    __syncthreads();

    // ---- attention phase 1: all 256 threads; 2 threads/pixel, 32 channels each ----
    float mk[9];
    {
        const int p  = tid & 127;
        const int c0 = (tid >> 7) * 32;
        const int jc = p + 1;
        float cx = sm[S_PN + TW + jc];
        float cy = sm[S_PN + 3*TW + TW + jc];
        float cz = sm[S_PN + 6*TW + TW + jc];
        float cr = sm[S_RNG + TW + jc];
        float p0x[9], p0y[9], p0z[9], p0r[9];
        const int* mrow = mask + (size_t)b * NPIX;
        #pragma unroll
        for (int k = 0; k < 9; k++) {
            int r = k/3, dj = k - r*3, off = r*TW + p + dj;
            p0x[k] = sm[S_PN + off]        - cx;
            p0y[k] = sm[S_PN + 3*TW + off] - cy;
            p0z[k] = sm[S_PN + 6*TW + off] - cz;
            p0r[k] = sm[S_RNG + off]       - cr;
            int gh = h + r - 1, gw = w0 + p + dj - 1;
            mk[k] = ((unsigned)gh < Hh && (unsigned)gw < Ww) ? (float)mrow[gh*Ww + gw] : 0.f;
        }
        float wsv[9];
        #pragma unroll
        for (int k = 0; k < 9; k++) wsv[k] = -1e30f;
        float wcmax = -1e30f;
        #pragma unroll 4
        for (int ci = 0; ci < 32; ci++) {
            int c = c0 + ci;
            float4 w4 = __ldg((const float4*)w_spatial + c);
            float4 v4 = __ldg((const float4*)w_channel + c);
            float bs = __ldg(b_spatial + c), bc = __ldg(b_channel + c);
            float wcc = -1e30f;
            #pragma unroll
            for (int k = 0; k < 9; k++) {
                float ds = fmaf(p0x[k], w4.x, fmaf(p0y[k], w4.y, fmaf(p0z[k], w4.z, fmaf(p0r[k], w4.w, bs))));
                float dc = fmaf(p0x[k], v4.x, fmaf(p0y[k], v4.y, fmaf(p0z[k], v4.z, fmaf(p0r[k], v4.w, bc))));
                wsv[k] = fmaxf(wsv[k], ds);
                wcc    = fmaxf(wcc, dc);
            }
            sm[S_WCP + c*132 + p] = wcc;          // raw channel score
            wcmax = fmaxf(wcmax, wcc);
        }
        #pragma unroll
        for (int k = 0; k < 9; k++) sm[S_WSP + tid*10 + k] = wsv[k];
        sm[S_WCM + tid] = wcmax;
    }
    __syncthreads();

    // ---- attention phase 2: threads 0..127 combine + softmax ----
    if (tid < 128) {
        const int p = tid;
        float wsv[9];
        #pragma unroll
        for (int k = 0; k < 9; k++)
            wsv[k] = fmaxf(sm[S_WSP + p*10 + k], sm[S_WSP + (p+128)*10 + k]);
        float wcmax = fmaxf(sm[S_WCM + p], sm[S_WCM + p + 128]);
        float wmax = wsv[0];
        #pragma unroll
        for (int k = 1; k < 9; k++) wmax = fmaxf(wmax, wsv[k]);
        float ssum = 0.f;
        #pragma unroll
        for (int k = 0; k < 9; k++) { wsv[k] = __expf(wsv[k] - wmax); ssum += wsv[k]; }
        float sinv = 1.f / ssum;
        #pragma unroll
        for (int k = 0; k < 9; k++) {
            sm[S_A1 + k*132 + p] = wsv[k]*sinv*mk[k];
            sm[S_M  + k*132 + p] = mk[k];
        }
        float csum = 0.f;
        #pragma unroll 8
        for (int c = 0; c < 64; c++) {
            float e = __expf(sm[S_WCP + c*132 + p] - wcmax);
            sm[S_WCP + c*132 + p] = e;
            csum += e;
        }
        float cinv = 1.f / csum;
        #pragma unroll 8
        for (int c = 0; c < 64; c++)
            sm[S_WCP + c*132 + p] *= cinv;
    }

    // ---- GEMM: 4 pixels x 8 outputs per thread ----
    unsigned long long acc[16];
    #pragma unroll
    for (int i = 0; i < 16; i++) acc[i] = 0ull;

    const int mp  = tid & 127;            // pixel
    const int mc0 = (tid >> 7) * 32;      // channel start

    // prefetch A tile for k=0 (4 float4 per thread)
    float4 pA[4];
    {
        const float4* src = (const float4*)g_aggT;
        #pragma unroll
        for (int t = 0; t < 4; t++) pA[t] = src[t*256 + tid];
    }

    for (int k9 = 0; k9 < 9; k9++) {
        __syncthreads();   // previous k's s_A/s_W reads complete
        // store prefetched A[k9]
        {
            float4* dst = (float4*)(sm + S_A);
            #pragma unroll
            for (int t = 0; t < 4; t++) dst[t*256 + tid] = pA[t];
        }
        // materialize W[c][p]
        {
            const int rr = k9/3, dj = k9 - rr*3;
            const int gh = h + rr - 1, gw = w0 + mp + dj - 1;
            const bool valid = ((unsigned)gh < Hh) && ((unsigned)gw < Ww);
            const float* fptr = xb + (size_t)(3 + mc0)*NPIX + (size_t)gh*Ww + gw;
            float amk = sm[S_A1 + k9*132 + mp];
            float mkk = sm[S_M  + k9*132 + mp];
            #pragma unroll 8
            for (int cc = 0; cc < 32; cc++) {
                float fv = valid ? __ldg(fptr + (size_t)cc*NPIX) : 0.f;
                float wf = fmaf(mkk, sm[S_WCP + (mc0 + cc)*132 + mp], amk) * fv;
                sm[S_W + (mc0 + cc)*136 + mp] = wf;
            }
        }
        __syncthreads();

        // prefetch A for k9+1 (hides under GEMM below)
        if (k9 < 8) {
            const float4* src = (const float4*)(g_aggT + (k9+1)*4096);
            #pragma unroll
            for (int t = 0; t < 4; t++) pA[t] = src[t*256 + tid];
        }

        #pragma unroll 2
        for (int c = 0; c < 64; c++) {
            float4 wv = *(const float4*)(sm + S_W + c*136 + pg*4);
            const ulonglong2* ar = (const ulonglong2*)(sm + S_A + c*64 + og*8);
            ulonglong2 aL = ar[0];   // output pairs (o0,o1),(o2,o3)
            ulonglong2 aH = ar[1];   // (o4,o5),(o6,o7)
            #define DO_PIX(i, w) { \
                unsigned long long wf2; \
                asm("mov.b64 %0, {%1, %1};" : "=l"(wf2) : "f"(w)); \
                asm("fma.rn.f32x2 %0, %1, %2, %0;" : "+l"(acc[(i)*4+0]) : "l"(aL.x), "l"(wf2)); \
                asm("fma.rn.f32x2 %0, %1, %2, %0;" : "+l"(acc[(i)*4+1]) : "l"(aL.y), "l"(wf2)); \
                asm("fma.rn.f32x2 %0, %1, %2, %0;" : "+l"(acc[(i)*4+2]) : "l"(aH.x), "l"(wf2)); \
                asm("fma.rn.f32x2 %0, %1, %2, %0;" : "+l"(acc[(i)*4+3]) : "l"(aH.y), "l"(wf2)); }
            DO_PIX(0, wv.x) DO_PIX(1, wv.y) DO_PIX(2, wv.z) DO_PIX(3, wv.w)
            #undef DO_PIX
        }
    }

    // ---- epilogue: stage [o][p] in s_W ----
    __syncthreads();
    #pragma unroll
    for (int i = 0; i < 4; i++) {
        #pragma unroll
        for (int j = 0; j < 4; j++) {
            float lo, hi;
            asm("mov.b64 {%0, %1}, %2;" : "=f"(lo), "=f"(hi) : "l"(acc[i*4+j]));
            sm[S_W + (og*8 + 2*j    )*136 + pg*4 + i] = lo;
            sm[S_W + (og*8 + 2*j + 1)*136 + pg*4 + i] = hi;
        }
    }
    __syncthreads();
    {
        const size_t n0 = (size_t)h * Ww + w0;
        float* gp = g_pre + (size_t)b * COUTC * NPIX;
        #pragma unroll
        for (int t = 0; t < 8; t++) {
            int idx = t*256 + tid;        // 0..2047 float4s
            int o = idx >> 5, p4 = idx & 31;
            float4 v = *(const float4*)&sm[S_W + o*136 + p4*4];
            *(float4*)(gp + (size_t)o*NPIX + n0 + p4*4) = v;
        }
    }
}

__global__ void k_stats() {
    int o = blockIdx.x, slab = blockIdx.y, tid = threadIdx.x;
    size_t base = (slab < 8)
        ? ((size_t)o * NPIX + (size_t)slab * 16384)
        : ((size_t)(COUTC + o) * NPIX + (size_t)(slab - 8) * 16384);
    const float4* p = (const float4*)(g_pre + base);
    float s = 0.f, s2 = 0.f;
    #pragma unroll 4
    for (int i = tid; i < 4096; i += 256) {
        float4 v = p[i];
        s  += v.x + v.y + v.z + v.w;
        s2 += v.x*v.x + v.y*v.y + v.z*v.z + v.w*v.w;
    }
    #pragma unroll
    for (int off = 16; off; off >>= 1) {
        s  += __shfl_down_sync(0xffffffffu, s,  off);
        s2 += __shfl_down_sync(0xffffffffu, s2, off);
    }
    __shared__ float rs[8], rq[8];
    int wrp = tid >> 5, lane = tid & 31;
    if (lane == 0) { rs[wrp] = s; rq[wrp] = s2; }
    __syncthreads();
    if (tid == 0) {
        float a = 0.f, q = 0.f;
        #pragma unroll
        for (int i = 0; i < 8; i++) { a += rs[i]; q += rq[i]; }
        atomicAdd(&g_sum[o],   (double)a);
        atomicAdd(&g_sumsq[o], (double)q);
    }
}

__global__ void k_final(const float* __restrict__ gamma, const float* __restrict__ beta) {
    int o = threadIdx.x;
    double N = (double)NTOT;
    double mean = g_sum[o] / N;
    double var  = g_sumsq[o] / N - mean * mean;
    if (var < 0.0) var = 0.0;
    float sc = gamma[o] * (float)(1.0 / sqrt(var + 1e-5));
    g_scale[o] = sc;
    g_shift[o] = beta[o] - (float)mean * sc;
}

__global__ void k_norm(float* __restrict__ out) {
    int i = blockIdx.x * 256 + threadIdx.x;
    float4 v = ((const float4*)g_pre)[i];
    int o = (i >> 15) & 63;
    float sc = g_scale[o], sh = g_shift[o];
    float4 r;
    r.x = fmaxf(0.f, v.x * sc + sh);
    r.y = fmaxf(0.f, v.y * sc + sh);
    r.z = fmaxf(0.f, v.z * sc + sh);
    r.w = fmaxf(0.f, v.w * sc + sh);
    ((float4*)out)[i] = r;
}

extern "C" void kernel_launch(void* const* d_in, const int* in_sizes, int n_in,
                              void* d_out, int out_size) {
    const float* x         = (const float*)d_in[0];
    const int*   mask      = (const int*)  d_in[1];
    const float* w_spatial = (const float*)d_in[2];
    const float* b_spatial = (const float*)d_in[3];
    const float* w_channel = (const float*)d_in[4];
    const float* b_channel = (const float*)d_in[5];
    const float* w_agg     = (const float*)d_in[6];
    const float* gamma     = (const float*)d_in[7];
    const float* beta      = (const float*)d_in[8];
    float* out = (float*)d_out;

    cudaFuncSetAttribute(k_main, cudaFuncAttributeMaxDynamicSharedMemorySize, SMEM_BYTES);

    k_prep<<<144, 256>>>(w_agg);
    dim3 grid(Ww / TILE, Hh, Bn);   // (16, 64, 2) = 2048 CTAs, 2 per SM
    k_main<<<grid, THREADS, SMEM_BYTES>>>(x, mask, w_spatial, b_spatial, w_channel, b_channel);
    k_stats<<<dim3(COUTC, 16), 256>>>();
    k_final<<<1, COUTC>>>(gamma, beta);
    k_norm<<<16384, 256>>>(out);
}